// round 6
// baseline (speedup 1.0000x reference)
#include <cuda_runtime.h>
#include <cstdint>

#define HH   480
#define WW   640
#define DIMC 32
#define NB   8
#define HWSZ (HH * WW)          // 307,200 sites per batch plane

// Per-BATCH scratch (39.3 MB + 1.2 MB) — small enough to stay L2-resident.
// Zero-initialized at module load; every finalize restores zeros, so the
// "scratch == 0 on entry" invariant holds for every call (deterministic).
__device__ float g_sum[(size_t)HWSZ * DIMC];
__device__ float g_cnt[HWSZ];
__device__ int   g_off[NB];     // canonical int32 cumulative offsets

// Normalize offsets to int32 whether the harness stored int64 or int32.
// int64 LE: words = [v0, 0, v1, 0, ...]; int32: words = [v0, v1, ...], v1 != 0.
__global__ void prep_offsets_kernel(const int* __restrict__ o32)
{
    bool is64 = (o32[1] == 0);
#pragma unroll
    for (int i = 0; i < NB; i++)
        g_off[i] = is64 ? o32[2 * i] : o32[i];
}

// 8 threads per event, one float4 vector-RED each (channels part*4..+3).
// Only events belonging to batch `b` do work; others exit before any
// event/feature load (the guard reads only g_off, L1/L2-hot).
__global__ void scatter_kernel(const float* __restrict__ events,
                               const float* __restrict__ features,
                               int n, int b)
{
    int t = blockIdx.x * blockDim.x + threadIdx.x;
    int e = t >> 3;
    if (e >= n) return;

    int lo = (b == 0) ? 0 : g_off[b - 1];
    int hi = g_off[b];
    if (e < lo || e >= hi) return;

    int part = t & 7;

    float2 ev = __ldg((const float2*)events + e);

    // jnp.round == round-half-even == __float2int_rn; then clip
    int x = __float2int_rn(ev.x * (float)WW);
    int y = __float2int_rn(ev.y * (float)HH);
    x = min(max(x, 0), WW - 1);
    y = min(max(y, 0), HH - 1);

    int pix = y * WW + x;       // within-plane site

    float4 f = __ldg((const float4*)features + (size_t)e * 8 + part);

    float* dst = g_sum + (size_t)pix * DIMC + part * 4;
    asm volatile("red.global.add.v4.f32 [%0], {%1, %2, %3, %4};"
                 :: "l"(dst), "f"(f.x), "f"(f.y), "f"(f.z), "f"(f.w)
                 : "memory");
    if (part == 0) {
        asm volatile("red.global.add.f32 [%0], %1;"
                     :: "l"(g_cnt + pix), "f"(1.0f)
                     : "memory");
    }
}

// One block per 32 consecutive sites of plane b: read [site,32] (L2-resident),
// normalize, transpose via smem, write out[b,:,:,:] coalesced as float4,
// then restore zeros to the scratch lines just consumed (replaces memset).
__global__ void finalize_kernel(float* __restrict__ out, int b)
{
    __shared__ float s[32][33];
    __shared__ float sinv[32];

    int tid  = threadIdx.x;            // 0..255
    int pix0 = blockIdx.x * 32;

    {
        int p  = tid >> 3;
        int c0 = (tid & 7) * 4;
        float4* gsp = (float4*)g_sum + (size_t)pix0 * 8 + tid;
        float4 v = *gsp;
        s[p][c0 + 0] = v.x;
        s[p][c0 + 1] = v.y;
        s[p][c0 + 2] = v.z;
        s[p][c0 + 3] = v.w;
        *gsp = make_float4(0.f, 0.f, 0.f, 0.f);   // restore zero for next batch
    }
    if (tid < 32) {
        float c = g_cnt[pix0 + tid];
        sinv[tid] = 1.0f / fmaxf(c, 1.0f);
        g_cnt[pix0 + tid] = 0.0f;                  // restore zero
    }
    __syncthreads();

    int d   = tid >> 3;
    int px0 = (tid & 7) * 4;
    float4 o;
    o.x = s[px0 + 0][d] * sinv[px0 + 0];
    o.y = s[px0 + 1][d] * sinv[px0 + 1];
    o.z = s[px0 + 2][d] * sinv[px0 + 2];
    o.w = s[px0 + 3][d] * sinv[px0 + 3];

    // pix0 is a multiple of 32; W=640 so a 32-site tile never crosses a row.
    float4* orow = (float4*)(out + (size_t)b * DIMC * HWSZ + (size_t)d * HWSZ + pix0);
    orow[tid & 7] = o;
}

extern "C" void kernel_launch(void* const* d_in, const int* in_sizes, int n_in,
                              void* d_out, int out_size)
{
    const float* events   = (const float*)d_in[0];
    const float* features = (const float*)d_in[1];
    const int*   offs_raw = (const int*)d_in[2];
    int n = in_sizes[0] / 2;

    prep_offsets_kernel<<<1, 1>>>(offs_raw);

    const int threads = 256;
    int total  = n * 8;                               // 8 threads per event
    int blocks = (total + threads - 1) / threads;

    for (int b = 0; b < NB; b++) {
        scatter_kernel<<<blocks, threads>>>(events, features, n, b);
        finalize_kernel<<<HWSZ / 32, 256>>>((float*)d_out, b);
    }
}